// round 1
// baseline (speedup 1.0000x reference)
#include <cuda_runtime.h>
#include <cstdint>

// Problem constants (fixed by the dataset)
#define B_   2
#define S_   1024
#define D_   1024
#define VC_  8192
#define K_   4
#define V_   32000
#define BS_  (B_ * S_)   // 2048

// ---------------------------------------------------------------------------
// Device-global scratch (allocation-free rule: no cudaMalloc anywhere)
// ---------------------------------------------------------------------------
__device__ float          g_logits[BS_ * VC_];   // 64 MB intermediate logits
__device__ unsigned short g_codes[V_ * K_];      // 256 KB packed hash codes

// ---------------------------------------------------------------------------
// Kernel 1: hash code table.  code[v][k] = ((v*a[k]+b[k]) % p[k]) % VC
// v*a fits in int32 (32000*40009 < 2^31).  VC is a power of two -> mask.
// ---------------------------------------------------------------------------
__global__ void hash_kernel(const int* __restrict__ p,
                            const int* __restrict__ a,
                            const int* __restrict__ b) {
    int v = blockIdx.x * blockDim.x + threadIdx.x;
    if (v >= V_) return;
#pragma unroll
    for (int k = 0; k < K_; k++) {
        unsigned int h = (unsigned int)(v * a[k] + b[k]) % (unsigned int)p[k];
        g_codes[v * K_ + k] = (unsigned short)(h & (VC_ - 1));
    }
}

// ---------------------------------------------------------------------------
// Kernel 2: tf32 GEMM  logits[m][n] = sum_d X[m][d] * W[n][d]
// M=2048, N=8192, K=1024.  Tile 128x128x16, 256 threads (8 warps),
// warp tile 32m x 64n via mma.sync.m16n8k8 tf32.
// Smem rows padded to 20 floats: fragment LDS address (20*g + t) mod 32
// covers all 32 banks -> conflict-free fragment loads.
// ---------------------------------------------------------------------------
#define BM 128
#define BN 128
#define BK 16
#define APAD 20   // floats per smem row (16 data + 4 pad)

__device__ __forceinline__ unsigned int f2tf32(float f) {
    unsigned int u;
    asm("cvt.rna.tf32.f32 %0, %1;" : "=r"(u) : "f"(f));
    return u;
}

__global__ __launch_bounds__(256) void gemm_tf32(const float* __restrict__ X,
                                                 const float* __restrict__ W) {
    __shared__ float As[BM * APAD];
    __shared__ float Bs[BN * APAD];

    const int tid  = threadIdx.x;
    const int lane = tid & 31;
    const int warp = tid >> 5;
    const int wm   = (warp & 3) * 32;   // warp m offset inside tile
    const int wn   = (warp >> 2) * 64;  // warp n offset inside tile
    const int g    = lane >> 2;         // group id (0..7)
    const int t    = lane & 3;          // thread-in-group (0..3)

    const int rowBase = blockIdx.y * BM;
    const int colBase = blockIdx.x * BN;

    float acc[2][8][4];
#pragma unroll
    for (int mt = 0; mt < 2; mt++)
#pragma unroll
        for (int nt = 0; nt < 8; nt++)
#pragma unroll
            for (int i = 0; i < 4; i++) acc[mt][nt][i] = 0.0f;

    for (int kt = 0; kt < D_; kt += BK) {
        // ---- global -> smem (512 float4 per operand, 2 per thread) ----
#pragma unroll
        for (int i = 0; i < 2; i++) {
            int f  = tid + i * 256;          // 0..511
            int r  = f >> 2;                 // row in tile (0..127)
            int c4 = (f & 3) * 4;            // col (0,4,8,12)
            float4 va = *(const float4*)(X + (size_t)(rowBase + r) * D_ + kt + c4);
            va.x = __uint_as_float(f2tf32(va.x));
            va.y = __uint_as_float(f2tf32(va.y));
            va.z = __uint_as_float(f2tf32(va.z));
            va.w = __uint_as_float(f2tf32(va.w));
            *(float4*)(As + r * APAD + c4) = va;

            float4 vb = *(const float4*)(W + (size_t)(colBase + r) * D_ + kt + c4);
            vb.x = __uint_as_float(f2tf32(vb.x));
            vb.y = __uint_as_float(f2tf32(vb.y));
            vb.z = __uint_as_float(f2tf32(vb.z));
            vb.w = __uint_as_float(f2tf32(vb.w));
            *(float4*)(Bs + r * APAD + c4) = vb;
        }
        __syncthreads();

        // ---- 2 k-steps of 8 ----
#pragma unroll
        for (int s = 0; s < 2; s++) {
            unsigned int af[2][4];
            unsigned int bf[8][2];
#pragma unroll
            for (int mt = 0; mt < 2; mt++) {
                const float* ap = As + (wm + mt * 16 + g) * APAD + s * 8 + t;
                af[mt][0] = __float_as_uint(ap[0]);
                af[mt][1] = __float_as_uint(ap[8 * APAD]);
                af[mt][2] = __float_as_uint(ap[4]);
                af[mt][3] = __float_as_uint(ap[8 * APAD + 4]);
            }
#pragma unroll
            for (int nt = 0; nt < 8; nt++) {
                const float* bp = Bs + (wn + nt * 8 + g) * APAD + s * 8 + t;
                bf[nt][0] = __float_as_uint(bp[0]);
                bf[nt][1] = __float_as_uint(bp[4]);
            }
#pragma unroll
            for (int mt = 0; mt < 2; mt++)
#pragma unroll
                for (int nt = 0; nt < 8; nt++) {
                    asm volatile(
                        "mma.sync.aligned.m16n8k8.row.col.f32.tf32.tf32.f32 "
                        "{%0,%1,%2,%3},{%4,%5,%6,%7},{%8,%9},{%0,%1,%2,%3};"
                        : "+f"(acc[mt][nt][0]), "+f"(acc[mt][nt][1]),
                          "+f"(acc[mt][nt][2]), "+f"(acc[mt][nt][3])
                        : "r"(af[mt][0]), "r"(af[mt][1]),
                          "r"(af[mt][2]), "r"(af[mt][3]),
                          "r"(bf[nt][0]), "r"(bf[nt][1]));
                }
        }
        __syncthreads();
    }

    // ---- epilogue: write logits ----
#pragma unroll
    for (int mt = 0; mt < 2; mt++) {
#pragma unroll
        for (int nt = 0; nt < 8; nt++) {
            int r0 = rowBase + wm + mt * 16 + g;
            int c0 = colBase + wn + nt * 8 + 2 * t;
            *(float2*)(g_logits + (size_t)r0 * VC_ + c0) =
                make_float2(acc[mt][nt][0], acc[mt][nt][1]);
            *(float2*)(g_logits + (size_t)(r0 + 8) * VC_ + c0) =
                make_float2(acc[mt][nt][2], acc[mt][nt][3]);
        }
    }
}

// ---------------------------------------------------------------------------
// Kernel 3: gather.  One CTA per (b,s) row.  Row (32 KB) staged in smem,
// each thread handles 4 consecutive v per chunk (uint4 code loads, STG.128).
// ---------------------------------------------------------------------------
__global__ __launch_bounds__(512) void gather_kernel(float* __restrict__ out) {
    __shared__ float row[VC_];
    const int bs  = blockIdx.x;
    const int tid = threadIdx.x;

    const float* lrow = g_logits + (size_t)bs * VC_;
#pragma unroll
    for (int i = 0; i < 4; i++) {
        int idx = i * 2048 + tid * 4;
        *(float4*)(row + idx) = *(const float4*)(lrow + idx);
    }
    __syncthreads();

    float* orow = out + (size_t)bs * V_;
#pragma unroll
    for (int c = 0; c < 16; c++) {
        int v0 = c * 2048 + tid * 4;
        if (v0 < V_) {
            const uint4* cp = (const uint4*)(g_codes + (size_t)v0 * K_);
            uint4 p0 = cp[0];   // codes for v0, v0+1
            uint4 p1 = cp[1];   // codes for v0+2, v0+3
            float4 r;
            r.x = 0.25f * (row[p0.x & 0xFFFF] + row[p0.x >> 16] +
                           row[p0.y & 0xFFFF] + row[p0.y >> 16]);
            r.y = 0.25f * (row[p0.z & 0xFFFF] + row[p0.z >> 16] +
                           row[p0.w & 0xFFFF] + row[p0.w >> 16]);
            r.z = 0.25f * (row[p1.x & 0xFFFF] + row[p1.x >> 16] +
                           row[p1.y & 0xFFFF] + row[p1.y >> 16]);
            r.w = 0.25f * (row[p1.z & 0xFFFF] + row[p1.z >> 16] +
                           row[p1.w & 0xFFFF] + row[p1.w >> 16]);
            *(float4*)(orow + v0) = r;
        }
    }
}

// ---------------------------------------------------------------------------
// Launch
// ---------------------------------------------------------------------------
extern "C" void kernel_launch(void* const* d_in, const int* in_sizes, int n_in,
                              void* d_out, int out_size) {
    const float* x = (const float*)d_in[0];
    const float* W = (const float*)d_in[1];
    const int*   p = (const int*)d_in[2];
    const int*   a = (const int*)d_in[3];
    const int*   b = (const int*)d_in[4];
    float* out = (float*)d_out;

    hash_kernel<<<(V_ + 255) / 256, 256>>>(p, a, b);

    dim3 ggrid(VC_ / BN, BS_ / BM);   // (64, 16)
    gemm_tf32<<<ggrid, 256>>>(x, W);

    gather_kernel<<<BS_, 512>>>(out);
}

// round 2
// speedup vs baseline: 1.0664x; 1.0664x over previous
#include <cuda_runtime.h>
#include <cstdint>

// Problem constants (fixed by the dataset)
#define B_   2
#define S_   1024
#define D_   1024
#define VC_  8192
#define K_   4
#define V_   32000
#define BS_  (B_ * S_)   // 2048

// ---------------------------------------------------------------------------
// Device-global scratch (allocation-free rule: no cudaMalloc anywhere)
// ---------------------------------------------------------------------------
__device__ float          g_logits[BS_ * VC_];   // 64 MB intermediate logits
__device__ unsigned short g_codes[V_ * K_];      // 256 KB packed hash codes

// ---------------------------------------------------------------------------
// Kernel 1: hash code table.  code[v][k] = ((v*a[k]+b[k]) % p[k]) % VC
// ---------------------------------------------------------------------------
__global__ void hash_kernel(const int* __restrict__ p,
                            const int* __restrict__ a,
                            const int* __restrict__ b) {
    int v = blockIdx.x * blockDim.x + threadIdx.x;
    if (v >= V_) return;
#pragma unroll
    for (int k = 0; k < K_; k++) {
        unsigned int h = (unsigned int)(v * a[k] + b[k]) % (unsigned int)p[k];
        g_codes[v * K_ + k] = (unsigned short)(h & (VC_ - 1));
    }
}

// ---------------------------------------------------------------------------
// Kernel 2: tf32 GEMM  logits[m][n] = sum_d X[m][d] * W[n][d]
// M=2048, N=8192, K=1024.  Tile 128x128x16, 256 threads (8 warps),
// warp tile 32m x 64n via mma.sync.m16n8k8 tf32.
// Register-prefetch + double-buffered smem: one __syncthreads per k-iter,
// LDG for tile k+1 overlaps MMA issue for tile k.
// ---------------------------------------------------------------------------
#define BM 128
#define BN 128
#define BK 16
#define APAD 20   // floats per smem row (16 data + 4 pad)

__device__ __forceinline__ unsigned int f2tf32(float f) {
    unsigned int u;
    asm("cvt.rna.tf32.f32 %0, %1;" : "=r"(u) : "f"(f));
    return u;
}

__global__ __launch_bounds__(256) void gemm_tf32(const float* __restrict__ X,
                                                 const float* __restrict__ W) {
    __shared__ float As[2][BM * APAD];
    __shared__ float Bs[2][BM * APAD];

    const int tid  = threadIdx.x;
    const int lane = tid & 31;
    const int warp = tid >> 5;
    const int wm   = (warp & 3) * 32;   // warp m offset inside tile
    const int wn   = (warp >> 2) * 64;  // warp n offset inside tile
    const int g    = lane >> 2;         // group id (0..7)
    const int t    = lane & 3;          // thread-in-group (0..3)

    const int rowBase = blockIdx.y * BM;
    const int colBase = blockIdx.x * BN;

    // per-thread global-load coordinates (2 float4 per operand)
    const int r0 = tid >> 2;            // 0..63
    const int c4 = (tid & 3) * 4;       // 0,4,8,12
    const float* gA0 = X + (size_t)(rowBase + r0) * D_ + c4;
    const float* gA1 = X + (size_t)(rowBase + r0 + 64) * D_ + c4;
    const float* gB0 = W + (size_t)(colBase + r0) * D_ + c4;
    const float* gB1 = W + (size_t)(colBase + r0 + 64) * D_ + c4;

    float acc[2][8][4];
#pragma unroll
    for (int mt = 0; mt < 2; mt++)
#pragma unroll
        for (int nt = 0; nt < 8; nt++)
#pragma unroll
            for (int i = 0; i < 4; i++) acc[mt][nt][i] = 0.0f;

    float4 pa0, pa1, pb0, pb1;

    // ---- prologue: load k-tile 0, convert, store to buf 0 ----
    pa0 = *(const float4*)(gA0);
    pa1 = *(const float4*)(gA1);
    pb0 = *(const float4*)(gB0);
    pb1 = *(const float4*)(gB1);
    {
        float* as = As[0] + r0 * APAD + c4;
        float* bs = Bs[0] + r0 * APAD + c4;
        as[0] = __uint_as_float(f2tf32(pa0.x)); as[1] = __uint_as_float(f2tf32(pa0.y));
        as[2] = __uint_as_float(f2tf32(pa0.z)); as[3] = __uint_as_float(f2tf32(pa0.w));
        as += 64 * APAD;
        as[0] = __uint_as_float(f2tf32(pa1.x)); as[1] = __uint_as_float(f2tf32(pa1.y));
        as[2] = __uint_as_float(f2tf32(pa1.z)); as[3] = __uint_as_float(f2tf32(pa1.w));
        bs[0] = __uint_as_float(f2tf32(pb0.x)); bs[1] = __uint_as_float(f2tf32(pb0.y));
        bs[2] = __uint_as_float(f2tf32(pb0.z)); bs[3] = __uint_as_float(f2tf32(pb0.w));
        bs += 64 * APAD;
        bs[0] = __uint_as_float(f2tf32(pb1.x)); bs[1] = __uint_as_float(f2tf32(pb1.y));
        bs[2] = __uint_as_float(f2tf32(pb1.z)); bs[3] = __uint_as_float(f2tf32(pb1.w));
    }
    __syncthreads();

    int buf = 0;
    for (int kt = BK; kt <= D_; kt += BK) {
        // -- prefetch next tile's global data (overlaps with compute below) --
        const bool has_next = (kt < D_);
        if (has_next) {
            pa0 = *(const float4*)(gA0 + kt);
            pa1 = *(const float4*)(gA1 + kt);
            pb0 = *(const float4*)(gB0 + kt);
            pb1 = *(const float4*)(gB1 + kt);
        }

        // -- compute from smem[buf] --
#pragma unroll
        for (int s = 0; s < 2; s++) {
            unsigned int af[2][4];
            unsigned int bf[8][2];
#pragma unroll
            for (int mt = 0; mt < 2; mt++) {
                const float* ap = As[buf] + (wm + mt * 16 + g) * APAD + s * 8 + t;
                af[mt][0] = __float_as_uint(ap[0]);
                af[mt][1] = __float_as_uint(ap[8 * APAD]);
                af[mt][2] = __float_as_uint(ap[4]);
                af[mt][3] = __float_as_uint(ap[8 * APAD + 4]);
            }
#pragma unroll
            for (int nt = 0; nt < 8; nt++) {
                const float* bp = Bs[buf] + (wn + nt * 8 + g) * APAD + s * 8 + t;
                bf[nt][0] = __float_as_uint(bp[0]);
                bf[nt][1] = __float_as_uint(bp[4]);
            }
#pragma unroll
            for (int mt = 0; mt < 2; mt++)
#pragma unroll
                for (int nt = 0; nt < 8; nt++) {
                    asm volatile(
                        "mma.sync.aligned.m16n8k8.row.col.f32.tf32.tf32.f32 "
                        "{%0,%1,%2,%3},{%4,%5,%6,%7},{%8,%9},{%0,%1,%2,%3};"
                        : "+f"(acc[mt][nt][0]), "+f"(acc[mt][nt][1]),
                          "+f"(acc[mt][nt][2]), "+f"(acc[mt][nt][3])
                        : "r"(af[mt][0]), "r"(af[mt][1]),
                          "r"(af[mt][2]), "r"(af[mt][3]),
                          "r"(bf[nt][0]), "r"(bf[nt][1]));
                }
        }

        // -- store prefetched tile into the other buffer --
        if (has_next) {
            int nb = buf ^ 1;
            float* as = As[nb] + r0 * APAD + c4;
            float* bs = Bs[nb] + r0 * APAD + c4;
            as[0] = __uint_as_float(f2tf32(pa0.x)); as[1] = __uint_as_float(f2tf32(pa0.y));
            as[2] = __uint_as_float(f2tf32(pa0.z)); as[3] = __uint_as_float(f2tf32(pa0.w));
            as += 64 * APAD;
            as[0] = __uint_as_float(f2tf32(pa1.x)); as[1] = __uint_as_float(f2tf32(pa1.y));
            as[2] = __uint_as_float(f2tf32(pa1.z)); as[3] = __uint_as_float(f2tf32(pa1.w));
            bs[0] = __uint_as_float(f2tf32(pb0.x)); bs[1] = __uint_as_float(f2tf32(pb0.y));
            bs[2] = __uint_as_float(f2tf32(pb0.z)); bs[3] = __uint_as_float(f2tf32(pb0.w));
            bs += 64 * APAD;
            bs[0] = __uint_as_float(f2tf32(pb1.x)); bs[1] = __uint_as_float(f2tf32(pb1.y));
            bs[2] = __uint_as_float(f2tf32(pb1.z)); bs[3] = __uint_as_float(f2tf32(pb1.w));
            __syncthreads();
            buf = nb;
        }
    }

    // ---- epilogue: write logits ----
#pragma unroll
    for (int mt = 0; mt < 2; mt++) {
#pragma unroll
        for (int nt = 0; nt < 8; nt++) {
            int r = rowBase + wm + mt * 16 + g;
            int c = colBase + wn + nt * 8 + 2 * t;
            *(float2*)(g_logits + (size_t)r * VC_ + c) =
                make_float2(acc[mt][nt][0], acc[mt][nt][1]);
            *(float2*)(g_logits + (size_t)(r + 8) * VC_ + c) =
                make_float2(acc[mt][nt][2], acc[mt][nt][3]);
        }
    }
}

// ---------------------------------------------------------------------------
// Kernel 3: gather.  TWO (b,s) rows per CTA staged in 64 KB dynamic smem.
// One code load feeds both rows (halves the 512 MB L2 code traffic).
// ---------------------------------------------------------------------------
__global__ __launch_bounds__(512) void gather_kernel(float* __restrict__ out) {
    extern __shared__ float rows[];          // 2 * 8192 floats
    const int bs0 = blockIdx.x * 2;
    const int tid = threadIdx.x;

    // stage 2 contiguous logits rows: 4096 float4, 8 per thread
    const float4* src = (const float4*)(g_logits + (size_t)bs0 * VC_);
    float4* dst = (float4*)rows;
#pragma unroll
    for (int i = 0; i < 8; i++) {
        int idx = i * 512 + tid;
        dst[idx] = src[idx];
    }
    __syncthreads();

    const float* r0 = rows;
    const float* r1 = rows + VC_;
    float* o0 = out + (size_t)bs0 * V_;
    float* o1 = o0 + V_;

#pragma unroll
    for (int c = 0; c < 16; c++) {
        int v0 = c * 2048 + tid * 4;
        if (v0 < V_) {
            const uint4* cp = (const uint4*)(g_codes + (size_t)v0 * K_);
            uint4 p0 = cp[0];   // codes for v0, v0+1
            uint4 p1 = cp[1];   // codes for v0+2, v0+3
            int i0 = p0.x & 0xFFFF, i1 = p0.x >> 16, i2 = p0.y & 0xFFFF, i3 = p0.y >> 16;
            int i4 = p0.z & 0xFFFF, i5 = p0.z >> 16, i6 = p0.w & 0xFFFF, i7 = p0.w >> 16;
            int i8 = p1.x & 0xFFFF, i9 = p1.x >> 16, iA = p1.y & 0xFFFF, iB = p1.y >> 16;
            int iC = p1.z & 0xFFFF, iD = p1.z >> 16, iE = p1.w & 0xFFFF, iF = p1.w >> 16;

            float4 u;
            u.x = 0.25f * (r0[i0] + r0[i1] + r0[i2] + r0[i3]);
            u.y = 0.25f * (r0[i4] + r0[i5] + r0[i6] + r0[i7]);
            u.z = 0.25f * (r0[i8] + r0[i9] + r0[iA] + r0[iB]);
            u.w = 0.25f * (r0[iC] + r0[iD] + r0[iE] + r0[iF]);
            *(float4*)(o0 + v0) = u;

            float4 w;
            w.x = 0.25f * (r1[i0] + r1[i1] + r1[i2] + r1[i3]);
            w.y = 0.25f * (r1[i4] + r1[i5] + r1[i6] + r1[i7]);
            w.z = 0.25f * (r1[i8] + r1[i9] + r1[iA] + r1[iB]);
            w.w = 0.25f * (r1[iC] + r1[iD] + r1[iE] + r1[iF]);
            *(float4*)(o1 + v0) = w;
        }
    }
}

// ---------------------------------------------------------------------------
// Launch
// ---------------------------------------------------------------------------
extern "C" void kernel_launch(void* const* d_in, const int* in_sizes, int n_in,
                              void* d_out, int out_size) {
    const float* x = (const float*)d_in[0];
    const float* W = (const float*)d_in[1];
    const int*   p = (const int*)d_in[2];
    const int*   a = (const int*)d_in[3];
    const int*   b = (const int*)d_in[4];
    float* out = (float*)d_out;

    hash_kernel<<<(V_ + 255) / 256, 256>>>(p, a, b);

    dim3 ggrid(VC_ / BN, BS_ / BM);   // (64, 16)
    gemm_tf32<<<ggrid, 256>>>(x, W);

    const int gather_smem = 2 * VC_ * (int)sizeof(float);   // 64 KB
    cudaFuncSetAttribute(gather_kernel,
                         cudaFuncAttributeMaxDynamicSharedMemorySize, gather_smem);
    gather_kernel<<<BS_ / 2, 512, gather_smem>>>(out);
}

// round 4
// speedup vs baseline: 1.5380x; 1.4423x over previous
#include <cuda_runtime.h>
#include <cuda_fp16.h>
#include <cstdint>

// Problem constants (fixed by the dataset)
#define B_   2
#define S_   1024
#define D_   1024
#define VC_  8192
#define K_   4
#define V_   32000
#define BS_  (B_ * S_)   // 2048

// ---------------------------------------------------------------------------
// Device-global scratch (allocation-free rule)
// ---------------------------------------------------------------------------
__device__ float          g_logits[BS_ * VC_];   // 64 MB intermediate logits
__device__ unsigned short g_codes[V_ * K_];      // 256 KB packed hash codes

// ---------------------------------------------------------------------------
// Kernel 1: hash code table
// ---------------------------------------------------------------------------
__global__ void hash_kernel(const int* __restrict__ p,
                            const int* __restrict__ a,
                            const int* __restrict__ b) {
    int v = blockIdx.x * blockDim.x + threadIdx.x;
    if (v >= V_) return;
#pragma unroll
    for (int k = 0; k < K_; k++) {
        unsigned int h = (unsigned int)(v * a[k] + b[k]) % (unsigned int)p[k];
        g_codes[v * K_ + k] = (unsigned short)(h & (VC_ - 1));
    }
}

// ---------------------------------------------------------------------------
// Kernel 2: fp16 GEMM  logits[m][n] = sum_d X[m][d] * W[n][d]
// M=2048, N=8192, K=1024.  Tile 128x128x32, 256 threads (8 warps),
// warp tile 32m x 64n via mma.sync.m16n8k16.f16 (fp32 accum).
// Smem rows padded to 40 halves (80B): fragment b32 load bank =
// (20g + t) mod 32 -> all 32 banks, conflict-free.
// Register-prefetch double-buffer: one __syncthreads per k-iter.
// ---------------------------------------------------------------------------
#define BM 128
#define BN 128
#define BK 32
#define HPAD 40   // halves per smem row (32 data + 8 pad)

__device__ __forceinline__ uint32_t h2pack(float lo, float hi) {
    __half2 h = __floats2half2_rn(lo, hi);
    return *(uint32_t*)&h;
}

__global__ __launch_bounds__(256) void gemm_f16(const float* __restrict__ X,
                                                const float* __restrict__ W) {
    __shared__ __half As[2][BM * HPAD];
    __shared__ __half Bs[2][BM * HPAD];

    const int tid  = threadIdx.x;
    const int lane = tid & 31;
    const int warp = tid >> 5;
    const int wm   = (warp & 3) * 32;   // warp m offset inside tile
    const int wn   = (warp >> 2) * 64;  // warp n offset inside tile
    const int g    = lane >> 2;         // group id (0..7)
    const int t    = lane & 3;          // thread-in-group (0..3)

    const int rowBase = blockIdx.y * BM;
    const int colBase = blockIdx.x * BN;

    // per-thread global-load coordinates: 4 float4 per operand per k-iter
    // f = tid + i*256 (i<4) -> r = f>>3 (0..127), c4 = (f&7)*4 (0..28)
    const int r0 = tid >> 3;            // base row for i=0 (rows step 32 per i)
    const int c4 = (tid & 7) * 4;

    float acc[2][8][4];
#pragma unroll
    for (int mt = 0; mt < 2; mt++)
#pragma unroll
        for (int nt = 0; nt < 8; nt++)
#pragma unroll
            for (int i = 0; i < 4; i++) acc[mt][nt][i] = 0.0f;

    uint32_t pa[4][2], pb[4][2];   // prefetched half-packed data (4 frags x 4 halves)

    // ---- helper lambdas (macros via immediate code) ----
#define LOAD_CONVERT(kt)                                                     \
    {                                                                        \
        _Pragma("unroll")                                                    \
        for (int i = 0; i < 4; i++) {                                        \
            int r = r0 + i * 32;                                             \
            float4 va = *(const float4*)(X + (size_t)(rowBase + r) * D_ + (kt) + c4); \
            pa[i][0] = h2pack(va.x, va.y);                                   \
            pa[i][1] = h2pack(va.z, va.w);                                   \
            float4 vb = *(const float4*)(W + (size_t)(colBase + r) * D_ + (kt) + c4); \
            pb[i][0] = h2pack(vb.x, vb.y);                                   \
            pb[i][1] = h2pack(vb.z, vb.w);                                   \
        }                                                                    \
    }

#define STORE_STAGE(buf)                                                     \
    {                                                                        \
        _Pragma("unroll")                                                    \
        for (int i = 0; i < 4; i++) {                                        \
            int r = r0 + i * 32;                                             \
            *(uint2*)(&As[buf][r * HPAD + c4]) = make_uint2(pa[i][0], pa[i][1]); \
            *(uint2*)(&Bs[buf][r * HPAD + c4]) = make_uint2(pb[i][0], pb[i][1]); \
        }                                                                    \
    }

    // ---- prologue ----
    LOAD_CONVERT(0);
    STORE_STAGE(0);
    __syncthreads();

    int buf = 0;
    for (int kt = BK; kt <= D_; kt += BK) {
        const bool has_next = (kt < D_);
        if (has_next) LOAD_CONVERT(kt);

        // -- compute from smem[buf]: 2 k-steps of 16 --
#pragma unroll
        for (int s = 0; s < 2; s++) {
            uint32_t af[2][4];
            uint32_t bf[8][2];
#pragma unroll
            for (int mt = 0; mt < 2; mt++) {
                const __half* ap = &As[buf][(wm + mt * 16 + g) * HPAD + s * 16 + 2 * t];
                af[mt][0] = *(const uint32_t*)(ap);
                af[mt][1] = *(const uint32_t*)(ap + 8 * HPAD);
                af[mt][2] = *(const uint32_t*)(ap + 8);
                af[mt][3] = *(const uint32_t*)(ap + 8 * HPAD + 8);
            }
#pragma unroll
            for (int nt = 0; nt < 8; nt++) {
                const __half* bp = &Bs[buf][(wn + nt * 8 + g) * HPAD + s * 16 + 2 * t];
                bf[nt][0] = *(const uint32_t*)(bp);
                bf[nt][1] = *(const uint32_t*)(bp + 8);
            }
#pragma unroll
            for (int mt = 0; mt < 2; mt++)
#pragma unroll
                for (int nt = 0; nt < 8; nt++) {
                    asm volatile(
                        "mma.sync.aligned.m16n8k16.row.col.f32.f16.f16.f32 "
                        "{%0,%1,%2,%3},{%4,%5,%6,%7},{%8,%9},{%0,%1,%2,%3};"
                        : "+f"(acc[mt][nt][0]), "+f"(acc[mt][nt][1]),
                          "+f"(acc[mt][nt][2]), "+f"(acc[mt][nt][3])
                        : "r"(af[mt][0]), "r"(af[mt][1]),
                          "r"(af[mt][2]), "r"(af[mt][3]),
                          "r"(bf[nt][0]), "r"(bf[nt][1]));
                }
        }

        if (has_next) {
            int nb = buf ^ 1;
            // STORE into other buffer
#pragma unroll
            for (int i = 0; i < 4; i++) {
                int r = r0 + i * 32;
                *(uint2*)(&As[nb][r * HPAD + c4]) = make_uint2(pa[i][0], pa[i][1]);
                *(uint2*)(&Bs[nb][r * HPAD + c4]) = make_uint2(pb[i][0], pb[i][1]);
            }
            __syncthreads();
            buf = nb;
        }
    }

    // ---- epilogue: write logits ----
#pragma unroll
    for (int mt = 0; mt < 2; mt++) {
#pragma unroll
        for (int nt = 0; nt < 8; nt++) {
            int r = rowBase + wm + mt * 16 + g;
            int c = colBase + wn + nt * 8 + 2 * t;
            *(float2*)(g_logits + (size_t)r * VC_ + c) =
                make_float2(acc[mt][nt][0], acc[mt][nt][1]);
            *(float2*)(g_logits + (size_t)(r + 8) * VC_ + c) =
                make_float2(acc[mt][nt][2], acc[mt][nt][3]);
        }
    }
#undef LOAD_CONVERT
#undef STORE_STAGE
}

// ---------------------------------------------------------------------------
// Kernel 3: gather.  TWO (b,s) rows per CTA staged in 64 KB dynamic smem.
// ---------------------------------------------------------------------------
__global__ __launch_bounds__(512) void gather_kernel(float* __restrict__ out) {
    extern __shared__ float rows[];          // 2 * 8192 floats
    const int bs0 = blockIdx.x * 2;
    const int tid = threadIdx.x;

    const float4* src = (const float4*)(g_logits + (size_t)bs0 * VC_);
    float4* dst = (float4*)rows;
#pragma unroll
    for (int i = 0; i < 8; i++) {
        int idx = i * 512 + tid;
        dst[idx] = src[idx];
    }
    __syncthreads();

    const float* r0 = rows;
    const float* r1 = rows + VC_;
    float* o0 = out + (size_t)bs0 * V_;
    float* o1 = o0 + V_;

#pragma unroll
    for (int c = 0; c < 16; c++) {
        int v0 = c * 2048 + tid * 4;
        if (v0 < V_) {
            const uint4* cp = (const uint4*)(g_codes + (size_t)v0 * K_);
            uint4 p0 = cp[0];
            uint4 p1 = cp[1];
            int i0 = p0.x & 0xFFFF, i1 = p0.x >> 16, i2 = p0.y & 0xFFFF, i3 = p0.y >> 16;
            int i4 = p0.z & 0xFFFF, i5 = p0.z >> 16, i6 = p0.w & 0xFFFF, i7 = p0.w >> 16;
            int i8 = p1.x & 0xFFFF, i9 = p1.x >> 16, iA = p1.y & 0xFFFF, iB = p1.y >> 16;
            int iC = p1.z & 0xFFFF, iD = p1.z >> 16, iE = p1.w & 0xFFFF, iF = p1.w >> 16;

            float4 u;
            u.x = 0.25f * (r0[i0] + r0[i1] + r0[i2] + r0[i3]);
            u.y = 0.25f * (r0[i4] + r0[i5] + r0[i6] + r0[i7]);
            u.z = 0.25f * (r0[i8] + r0[i9] + r0[iA] + r0[iB]);
            u.w = 0.25f * (r0[iC] + r0[iD] + r0[iE] + r0[iF]);
            *(float4*)(o0 + v0) = u;

            float4 w;
            w.x = 0.25f * (r1[i0] + r1[i1] + r1[i2] + r1[i3]);
            w.y = 0.25f * (r1[i4] + r1[i5] + r1[i6] + r1[i7]);
            w.z = 0.25f * (r1[i8] + r1[i9] + r1[iA] + r1[iB]);
            w.w = 0.25f * (r1[iC] + r1[iD] + r1[iE] + r1[iF]);
            *(float4*)(o1 + v0) = w;
        }
    }
}

// ---------------------------------------------------------------------------
// Launch
// ---------------------------------------------------------------------------
extern "C" void kernel_launch(void* const* d_in, const int* in_sizes, int n_in,
                              void* d_out, int out_size) {
    const float* x = (const float*)d_in[0];
    const float* W = (const float*)d_in[1];
    const int*   p = (const int*)d_in[2];
    const int*   a = (const int*)d_in[3];
    const int*   b = (const int*)d_in[4];
    float* out = (float*)d_out;

    hash_kernel<<<(V_ + 255) / 256, 256>>>(p, a, b);

    dim3 ggrid(VC_ / BN, BS_ / BM);   // (64, 16)
    gemm_f16<<<ggrid, 256>>>(x, W);

    const int gather_smem = 2 * VC_ * (int)sizeof(float);   // 64 KB
    cudaFuncSetAttribute(gather_kernel,
                         cudaFuncAttributeMaxDynamicSharedMemorySize, gather_smem);
    gather_kernel<<<BS_ / 2, 512, gather_smem>>>(out);
}

// round 5
// speedup vs baseline: 1.7507x; 1.1383x over previous
#include <cuda_runtime.h>
#include <cuda_fp16.h>
#include <cstdint>

// Problem constants (fixed by the dataset)
#define B_   2
#define S_   1024
#define D_   1024
#define VC_  8192
#define K_   4
#define V_   32000
#define BS_  (B_ * S_)   // 2048

// ---------------------------------------------------------------------------
// Device-global scratch (allocation-free rule)
// ---------------------------------------------------------------------------
__device__ __half         g_lh[BS_ * VC_];      // 32 MB f16 logits
__device__ __half         g_xh[BS_ * D_];       // 4 MB  f16 X
__device__ __half         g_wh[VC_ * D_];       // 16 MB f16 W
__device__ unsigned short g_codes[V_ * K_];     // 256 KB packed hash codes

// ---------------------------------------------------------------------------
// Kernel 1: hash code table
// ---------------------------------------------------------------------------
__global__ void hash_kernel(const int* __restrict__ p,
                            const int* __restrict__ a,
                            const int* __restrict__ b) {
    int v = blockIdx.x * blockDim.x + threadIdx.x;
    if (v >= V_) return;
#pragma unroll
    for (int k = 0; k < K_; k++) {
        unsigned int h = (unsigned int)(v * a[k] + b[k]) % (unsigned int)p[k];
        g_codes[v * K_ + k] = (unsigned short)(h & (VC_ - 1));
    }
}

// ---------------------------------------------------------------------------
// Kernel 1b: one-time f32 -> f16 conversion of X and W
// ---------------------------------------------------------------------------
#define NX4 ((BS_ * D_) / 4)   // 524288 float4
#define NW4 ((VC_ * D_) / 4)   // 2097152 float4
__global__ __launch_bounds__(256) void convert_kernel(const float* __restrict__ X,
                                                      const float* __restrict__ W) {
    int i = blockIdx.x * blockDim.x + threadIdx.x;
    if (i < NX4) {
        float4 v = ((const float4*)X)[i];
        __half2 h0 = __floats2half2_rn(v.x, v.y);
        __half2 h1 = __floats2half2_rn(v.z, v.w);
        ((uint2*)g_xh)[i] = make_uint2(*(uint32_t*)&h0, *(uint32_t*)&h1);
    } else if (i < NX4 + NW4) {
        int j = i - NX4;
        float4 v = ((const float4*)W)[j];
        __half2 h0 = __floats2half2_rn(v.x, v.y);
        __half2 h1 = __floats2half2_rn(v.z, v.w);
        ((uint2*)g_wh)[j] = make_uint2(*(uint32_t*)&h0, *(uint32_t*)&h1);
    }
}

// ---------------------------------------------------------------------------
// Kernel 2: fp16 GEMM  logits[m][n] = sum_d X[m][d] * W[n][d]  (f16 in/out)
// Tile 256x128x32, 512 threads (16 warps: 8 m-warps x 2 n-warps),
// warp tile 32m x 64n, mma.sync.m16n8k16 (fp32 accum).
// Fragments via ldmatrix.x4 (conflict-free on 80B pitch).
// Register-prefetch double-buffer, one __syncthreads per k-iter.
// ---------------------------------------------------------------------------
#define BM 256
#define BN 128
#define BK 32
#define HPAD 40   // halves per smem row (32 data + 8 pad) -> 80B pitch

#define AS_BYTES (BM * HPAD * 2)   // 20480
#define BS_BYTES (BN * HPAD * 2)   // 10240
#define GEMM_SMEM (2 * AS_BYTES + 2 * BS_BYTES)   // 61440

__device__ __forceinline__ uint32_t smem_u32(const void* p) {
    uint32_t a;
    asm("{ .reg .u64 t; cvta.to.shared.u64 t, %1; cvt.u32.u64 %0, t; }"
        : "=r"(a) : "l"(p));
    return a;
}

__device__ __forceinline__ void ldmx4(uint32_t& r0, uint32_t& r1,
                                      uint32_t& r2, uint32_t& r3, uint32_t addr) {
    asm volatile("ldmatrix.sync.aligned.m8n8.x4.shared.b16 {%0,%1,%2,%3}, [%4];"
                 : "=r"(r0), "=r"(r1), "=r"(r2), "=r"(r3) : "r"(addr));
}

__global__ __launch_bounds__(512, 1) void gemm_f16(void) {
    extern __shared__ __align__(16) char sm[];
    // layout: As[0], As[1], Bs[0], Bs[1]
    char* Asb[2] = { sm, sm + AS_BYTES };
    char* Bsb[2] = { sm + 2 * AS_BYTES, sm + 2 * AS_BYTES + BS_BYTES };

    const int tid  = threadIdx.x;
    const int lane = tid & 31;
    const int warp = tid >> 5;
    const int wm   = (warp & 7) * 32;   // 8 m-warps
    const int wn   = (warp >> 3) * 64;  // 2 n-warps
    const int g    = lane >> 2;
    const int t    = lane & 3;

    const int rowBase = blockIdx.y * BM;
    const int colBase = blockIdx.x * BN;

    // global load coords: A: 2 uint4/thread, B: 1 uint4/thread
    const int ra = tid >> 2;            // row for A i=0 (0..127), i=1 adds 128
    const int rb = tid >> 2;            // row for B (0..127)
    const int c8 = (tid & 3) * 8;       // half offset within 32

    // ldmatrix per-lane address components
    const int aRow = wm + (lane & 7) + ((lane & 8) ? 8 : 0);       // + mt*16
    const int aCol = (lane & 16) ? 8 : 0;                          // + s*16
    const int bRow = wn + (lane & 7) + ((lane & 16) ? 8 : 0);      // + ntp*16
    const int bCol = ((lane & 8) ? 8 : 0);                         // + s*16

    float acc[2][8][4];
#pragma unroll
    for (int mt = 0; mt < 2; mt++)
#pragma unroll
        for (int nt = 0; nt < 8; nt++)
#pragma unroll
            for (int i = 0; i < 4; i++) acc[mt][nt][i] = 0.0f;

    uint4 pa0, pa1, pbv;

#define LOAD_TILES(kt)                                                       \
    {                                                                        \
        pa0 = *(const uint4*)(g_xh + (size_t)(rowBase + ra) * D_ + (kt) + c8);       \
        pa1 = *(const uint4*)(g_xh + (size_t)(rowBase + ra + 128) * D_ + (kt) + c8); \
        pbv = *(const uint4*)(g_wh + (size_t)(colBase + rb) * D_ + (kt) + c8);       \
    }
#define STORE_TILES(bi)                                                      \
    {                                                                        \
        *(uint4*)(Asb[bi] + (ra * HPAD + c8) * 2)        = pa0;              \
        *(uint4*)(Asb[bi] + ((ra + 128) * HPAD + c8) * 2) = pa1;             \
        *(uint4*)(Bsb[bi] + (rb * HPAD + c8) * 2)        = pbv;              \
    }

    LOAD_TILES(0);
    STORE_TILES(0);
    __syncthreads();

    int buf = 0;
    for (int kt = BK; kt <= D_; kt += BK) {
        const bool has_next = (kt < D_);
        if (has_next) LOAD_TILES(kt);

        uint32_t asBase = smem_u32(Asb[buf]);
        uint32_t bsBase = smem_u32(Bsb[buf]);

#pragma unroll
        for (int s = 0; s < 2; s++) {
            uint32_t af[2][4];
            uint32_t bf[8][2];
#pragma unroll
            for (int mt = 0; mt < 2; mt++) {
                uint32_t addr = asBase +
                    (((aRow + mt * 16) * HPAD) + (aCol + s * 16)) * 2;
                ldmx4(af[mt][0], af[mt][1], af[mt][2], af[mt][3], addr);
            }
#pragma unroll
            for (int ntp = 0; ntp < 4; ntp++) {
                uint32_t addr = bsBase +
                    (((bRow + ntp * 16) * HPAD) + (bCol + s * 16)) * 2;
                ldmx4(bf[2 * ntp][0], bf[2 * ntp][1],
                      bf[2 * ntp + 1][0], bf[2 * ntp + 1][1], addr);
            }
#pragma unroll
            for (int mt = 0; mt < 2; mt++)
#pragma unroll
                for (int nt = 0; nt < 8; nt++) {
                    asm volatile(
                        "mma.sync.aligned.m16n8k16.row.col.f32.f16.f16.f32 "
                        "{%0,%1,%2,%3},{%4,%5,%6,%7},{%8,%9},{%0,%1,%2,%3};"
                        : "+f"(acc[mt][nt][0]), "+f"(acc[mt][nt][1]),
                          "+f"(acc[mt][nt][2]), "+f"(acc[mt][nt][3])
                        : "r"(af[mt][0]), "r"(af[mt][1]),
                          "r"(af[mt][2]), "r"(af[mt][3]),
                          "r"(bf[nt][0]), "r"(bf[nt][1]));
                }
        }

        if (has_next) {
            int nb = buf ^ 1;
            *(uint4*)(Asb[nb] + (ra * HPAD + c8) * 2)         = pa0;
            *(uint4*)(Asb[nb] + ((ra + 128) * HPAD + c8) * 2) = pa1;
            *(uint4*)(Bsb[nb] + (rb * HPAD + c8) * 2)         = pbv;
            __syncthreads();
            buf = nb;
        }
    }

    // epilogue: f16 logits, uint32 (half2) per 2 cols
#pragma unroll
    for (int mt = 0; mt < 2; mt++) {
#pragma unroll
        for (int nt = 0; nt < 8; nt++) {
            int r = rowBase + wm + mt * 16 + g;
            int c = colBase + wn + nt * 8 + 2 * t;
            __half2 h0 = __floats2half2_rn(acc[mt][nt][0], acc[mt][nt][1]);
            __half2 h1 = __floats2half2_rn(acc[mt][nt][2], acc[mt][nt][3]);
            *(uint32_t*)(g_lh + (size_t)r * VC_ + c)       = *(uint32_t*)&h0;
            *(uint32_t*)(g_lh + (size_t)(r + 8) * VC_ + c) = *(uint32_t*)&h1;
        }
    }
#undef LOAD_TILES
#undef STORE_TILES
}

// ---------------------------------------------------------------------------
// Kernel 3: gather.  FOUR (b,s) rows per CTA, f16, interleaved [j][r0..r3]
// in 64 KB smem: one LDS.64 serves 4 rows x 1 hash code.
// ---------------------------------------------------------------------------
__global__ __launch_bounds__(512) void gather4(float* __restrict__ out) {
    extern __shared__ __half sh[];       // 8192 * 4 halves = 64 KB
    const int bs0 = blockIdx.x * 4;
    const int tid = threadIdx.x;

    const __half* L = g_lh + (size_t)bs0 * VC_;
    // stage interleaved: thread handles j0 = 2*i, loads 2 halves from each row
    for (int i = tid; i < VC_ / 2; i += 512) {
        int j0 = i * 2;
        unsigned u0 = *(const unsigned*)(L + j0);
        unsigned u1 = *(const unsigned*)(L + VC_ + j0);
        unsigned u2 = *(const unsigned*)(L + 2 * VC_ + j0);
        unsigned u3 = *(const unsigned*)(L + 3 * VC_ + j0);
        *(uint2*)(sh + j0 * 4) =
            make_uint2(__byte_perm(u0, u1, 0x5410), __byte_perm(u2, u3, 0x5410));
        *(uint2*)(sh + (j0 + 1) * 4) =
            make_uint2(__byte_perm(u0, u1, 0x7632), __byte_perm(u2, u3, 0x7632));
    }
    __syncthreads();

    float* o0 = out + (size_t)bs0 * V_;
    float* o1 = o0 + V_;
    float* o2 = o1 + V_;
    float* o3 = o2 + V_;

#pragma unroll
    for (int c = 0; c < 16; c++) {
        int v0 = c * 2048 + tid * 4;
        if (v0 >= V_) break;
        const uint4* cp = (const uint4*)(g_codes + (size_t)v0 * K_);
        uint4 p0 = cp[0];
        uint4 p1 = cp[1];
        unsigned cw[8] = {p0.x, p0.y, p0.z, p0.w, p1.x, p1.y, p1.z, p1.w};

        float s0[4], s1[4], s2[4], s3[4];
#pragma unroll
        for (int vi = 0; vi < 4; vi++) {
            float a0 = 0.f, a1 = 0.f, a2 = 0.f, a3 = 0.f;
#pragma unroll
            for (int h = 0; h < 2; h++) {
                unsigned w = cw[vi * 2 + h];
                int ja = w & 0xFFFF, jb = w >> 16;
                uint2 qa = *(const uint2*)(sh + ja * 4);
                float2 fa01 = __half22float2(*(const __half2*)&qa.x);
                float2 fa23 = __half22float2(*(const __half2*)&qa.y);
                a0 += fa01.x; a1 += fa01.y; a2 += fa23.x; a3 += fa23.y;
                uint2 qb = *(const uint2*)(sh + jb * 4);
                float2 fb01 = __half22float2(*(const __half2*)&qb.x);
                float2 fb23 = __half22float2(*(const __half2*)&qb.y);
                a0 += fb01.x; a1 += fb01.y; a2 += fb23.x; a3 += fb23.y;
            }
            s0[vi] = a0 * 0.25f; s1[vi] = a1 * 0.25f;
            s2[vi] = a2 * 0.25f; s3[vi] = a3 * 0.25f;
        }
        *(float4*)(o0 + v0) = make_float4(s0[0], s0[1], s0[2], s0[3]);
        *(float4*)(o1 + v0) = make_float4(s1[0], s1[1], s1[2], s1[3]);
        *(float4*)(o2 + v0) = make_float4(s2[0], s2[1], s2[2], s2[3]);
        *(float4*)(o3 + v0) = make_float4(s3[0], s3[1], s3[2], s3[3]);
    }
}

// ---------------------------------------------------------------------------
// Launch
// ---------------------------------------------------------------------------
extern "C" void kernel_launch(void* const* d_in, const int* in_sizes, int n_in,
                              void* d_out, int out_size) {
    const float* x = (const float*)d_in[0];
    const float* W = (const float*)d_in[1];
    const int*   p = (const int*)d_in[2];
    const int*   a = (const int*)d_in[3];
    const int*   b = (const int*)d_in[4];
    float* out = (float*)d_out;

    hash_kernel<<<(V_ + 255) / 256, 256>>>(p, a, b);
    convert_kernel<<<(NX4 + NW4 + 255) / 256, 256>>>(x, W);

    cudaFuncSetAttribute(gemm_f16, cudaFuncAttributeMaxDynamicSharedMemorySize,
                         GEMM_SMEM);
    dim3 ggrid(VC_ / BN, BS_ / BM);   // (64, 8)
    gemm_f16<<<ggrid, 512, GEMM_SMEM>>>();

    const int gather_smem = VC_ * 4 * (int)sizeof(__half);   // 64 KB
    cudaFuncSetAttribute(gather4,
                         cudaFuncAttributeMaxDynamicSharedMemorySize, gather_smem);
    gather4<<<BS_ / 4, 512, gather_smem>>>(out);
}

// round 6
// speedup vs baseline: 1.8984x; 1.0844x over previous
#include <cuda_runtime.h>
#include <cuda_fp16.h>
#include <cstdint>

// Problem constants (fixed by the dataset)
#define B_   2
#define S_   1024
#define D_   1024
#define VC_  8192
#define K_   4
#define V_   32000
#define BS_  (B_ * S_)   // 2048

// ---------------------------------------------------------------------------
// Device-global scratch (allocation-free rule)
// ---------------------------------------------------------------------------
__device__ __half         g_lh[BS_ * VC_];      // 32 MB f16 logits
__device__ __half         g_xh[BS_ * D_];       // 4 MB  f16 X
__device__ __half         g_wh[VC_ * D_];       // 16 MB f16 W
__device__ unsigned short g_codes[V_ * K_];     // 256 KB packed hash codes

// ---------------------------------------------------------------------------
// Kernel 1: hash code table
// ---------------------------------------------------------------------------
__global__ void hash_kernel(const int* __restrict__ p,
                            const int* __restrict__ a,
                            const int* __restrict__ b) {
    int v = blockIdx.x * blockDim.x + threadIdx.x;
    if (v >= V_) return;
#pragma unroll
    for (int k = 0; k < K_; k++) {
        unsigned int h = (unsigned int)(v * a[k] + b[k]) % (unsigned int)p[k];
        g_codes[v * K_ + k] = (unsigned short)(h & (VC_ - 1));
    }
}

// ---------------------------------------------------------------------------
// Kernel 1b: one-time f32 -> f16 conversion of X and W
// ---------------------------------------------------------------------------
#define NX4 ((BS_ * D_) / 4)   // 524288 float4
#define NW4 ((VC_ * D_) / 4)   // 2097152 float4
__global__ __launch_bounds__(256) void convert_kernel(const float* __restrict__ X,
                                                      const float* __restrict__ W) {
    int i = blockIdx.x * blockDim.x + threadIdx.x;
    if (i < NX4) {
        float4 v = ((const float4*)X)[i];
        __half2 h0 = __floats2half2_rn(v.x, v.y);
        __half2 h1 = __floats2half2_rn(v.z, v.w);
        ((uint2*)g_xh)[i] = make_uint2(*(uint32_t*)&h0, *(uint32_t*)&h1);
    } else if (i < NX4 + NW4) {
        int j = i - NX4;
        float4 v = ((const float4*)W)[j];
        __half2 h0 = __floats2half2_rn(v.x, v.y);
        __half2 h1 = __floats2half2_rn(v.z, v.w);
        ((uint2*)g_wh)[j] = make_uint2(*(uint32_t*)&h0, *(uint32_t*)&h1);
    }
}

// ---------------------------------------------------------------------------
// Kernel 2: fp16 GEMM, 4-stage cp.async pipeline.
// Tile 256x128x32, 512 threads (8 m-warps x 2 n-warps, warp tile 32x64),
// mma.sync.m16n8k16 (fp32 accum), ldmatrix.x4 fragments (80B pitch,
// conflict-free).
// ---------------------------------------------------------------------------
#define BM 256
#define BN 128
#define BK 32
#define HPAD 40   // halves per smem row -> 80B pitch
#define NS 4      // pipeline stages

#define AS_BYTES (BM * HPAD * 2)   // 20480
#define BSB_BYTES (BN * HPAD * 2)  // 10240
#define GEMM_SMEM (NS * (AS_BYTES + BSB_BYTES))   // 122880

__device__ __forceinline__ uint32_t smem_u32(const void* p) {
    uint32_t a;
    asm("{ .reg .u64 t; cvta.to.shared.u64 t, %1; cvt.u32.u64 %0, t; }"
        : "=r"(a) : "l"(p));
    return a;
}
__device__ __forceinline__ void cpa16(uint32_t dst, const void* src) {
    asm volatile("cp.async.cg.shared.global [%0], [%1], 16;"
                 :: "r"(dst), "l"(src) : "memory");
}
#define CP_COMMIT() asm volatile("cp.async.commit_group;" ::: "memory")
#define CP_WAIT(n)  asm volatile("cp.async.wait_group %0;" :: "n"(n) : "memory")

__device__ __forceinline__ void ldmx4(uint32_t& r0, uint32_t& r1,
                                      uint32_t& r2, uint32_t& r3, uint32_t addr) {
    asm volatile("ldmatrix.sync.aligned.m8n8.x4.shared.b16 {%0,%1,%2,%3}, [%4];"
                 : "=r"(r0), "=r"(r1), "=r"(r2), "=r"(r3) : "r"(addr));
}

__global__ __launch_bounds__(512, 1) void gemm_f16(void) {
    extern __shared__ __align__(16) char sm[];
    const int tid  = threadIdx.x;
    const int lane = tid & 31;
    const int warp = tid >> 5;
    const int wm   = (warp & 7) * 32;   // 8 m-warps
    const int wn   = (warp >> 3) * 64;  // 2 n-warps
    const int g    = lane >> 2;
    const int t    = lane & 3;

    const int rowBase = blockIdx.y * BM;
    const int colBase = blockIdx.x * BN;

    const uint32_t smb = smem_u32(sm);

    // copy coordinates
    const int ra = tid >> 2;            // 0..127 (A rows; +128 for second)
    const int c8 = (tid & 3) * 8;       // half offset within 32

    const __half* gA0 = g_xh + (size_t)(rowBase + ra) * D_ + c8;
    const __half* gA1 = g_xh + (size_t)(rowBase + ra + 128) * D_ + c8;
    const __half* gB  = g_wh + (size_t)(colBase + ra) * D_ + c8;
    const uint32_t stA0 = (ra * HPAD + c8) * 2;
    const uint32_t stA1 = ((ra + 128) * HPAD + c8) * 2;
    const uint32_t stB  = (ra * HPAD + c8) * 2;

#define ISSUE_STAGE(stg)                                                     \
    {                                                                        \
        int _slot = (stg) & (NS - 1);                                        \
        int _kt = (stg) * BK;                                                \
        uint32_t _sA = smb + _slot * AS_BYTES;                               \
        uint32_t _sB = smb + NS * AS_BYTES + _slot * BSB_BYTES;              \
        cpa16(_sA + stA0, gA0 + _kt);                                        \
        cpa16(_sA + stA1, gA1 + _kt);                                        \
        cpa16(_sB + stB,  gB  + _kt);                                        \
        CP_COMMIT();                                                         \
    }

    // ldmatrix per-lane address components
    const int aRow = wm + (lane & 7) + ((lane & 8) ? 8 : 0);
    const int aCol = (lane & 16) ? 8 : 0;
    const int bRow = wn + (lane & 7) + ((lane & 16) ? 8 : 0);
    const int bCol = ((lane & 8) ? 8 : 0);

    float acc[2][8][4];
#pragma unroll
    for (int mt = 0; mt < 2; mt++)
#pragma unroll
        for (int nt = 0; nt < 8; nt++)
#pragma unroll
            for (int i = 0; i < 4; i++) acc[mt][nt][i] = 0.0f;

    // prologue: stages 0..NS-2
    ISSUE_STAGE(0);
    ISSUE_STAGE(1);
    ISSUE_STAGE(2);

    const int NCHUNK = D_ / BK;   // 32
    for (int c = 0; c < NCHUNK; c++) {
        if (c < NCHUNK - 2) { CP_WAIT(2); } else { CP_WAIT(0); }
        __syncthreads();

        const int slot = c & (NS - 1);
        uint32_t asBase = smb + slot * AS_BYTES;
        uint32_t bsBase = smb + NS * AS_BYTES + slot * BSB_BYTES;

#pragma unroll
        for (int s = 0; s < 2; s++) {
            uint32_t af[2][4];
            uint32_t bf[8][2];
#pragma unroll
            for (int mt = 0; mt < 2; mt++) {
                uint32_t addr = asBase +
                    (((aRow + mt * 16) * HPAD) + (aCol + s * 16)) * 2;
                ldmx4(af[mt][0], af[mt][1], af[mt][2], af[mt][3], addr);
            }
#pragma unroll
            for (int ntp = 0; ntp < 4; ntp++) {
                uint32_t addr = bsBase +
                    (((bRow + ntp * 16) * HPAD) + (bCol + s * 16)) * 2;
                ldmx4(bf[2 * ntp][0], bf[2 * ntp][1],
                      bf[2 * ntp + 1][0], bf[2 * ntp + 1][1], addr);
            }
#pragma unroll
            for (int mt = 0; mt < 2; mt++)
#pragma unroll
                for (int nt = 0; nt < 8; nt++) {
                    asm volatile(
                        "mma.sync.aligned.m16n8k16.row.col.f32.f16.f16.f32 "
                        "{%0,%1,%2,%3},{%4,%5,%6,%7},{%8,%9},{%0,%1,%2,%3};"
                        : "+f"(acc[mt][nt][0]), "+f"(acc[mt][nt][1]),
                          "+f"(acc[mt][nt][2]), "+f"(acc[mt][nt][3])
                        : "r"(af[mt][0]), "r"(af[mt][1]),
                          "r"(af[mt][2]), "r"(af[mt][3]),
                          "r"(bf[nt][0]), "r"(bf[nt][1]));
                }
        }

        // issue stage c+NS-1 (writes slot (c-1)%NS: safe — all warps passed
        // this iteration's barrier, so compute of iter c-1 is finished)
        if (c + NS - 1 < NCHUNK) ISSUE_STAGE(c + NS - 1);
    }

    // epilogue: f16 logits
#pragma unroll
    for (int mt = 0; mt < 2; mt++) {
#pragma unroll
        for (int nt = 0; nt < 8; nt++) {
            int r = rowBase + wm + mt * 16 + g;
            int c = colBase + wn + nt * 8 + 2 * t;
            __half2 h0 = __floats2half2_rn(acc[mt][nt][0], acc[mt][nt][1]);
            __half2 h1 = __floats2half2_rn(acc[mt][nt][2], acc[mt][nt][3]);
            *(uint32_t*)(g_lh + (size_t)r * VC_ + c)       = *(uint32_t*)&h0;
            *(uint32_t*)(g_lh + (size_t)(r + 8) * VC_ + c) = *(uint32_t*)&h1;
        }
    }
#undef ISSUE_STAGE
}

// ---------------------------------------------------------------------------
// Kernel 3: gather.  EIGHT (b,s) rows per CTA, f16, interleaved [j][r0..r7]
// in 128 KB smem: one LDS.128 serves 8 rows x 1 hash code.
// ---------------------------------------------------------------------------
__global__ __launch_bounds__(512) void gather8(float* __restrict__ out) {
    extern __shared__ __half sh[];       // 8192 * 8 halves = 128 KB
    const int bs0 = blockIdx.x * 8;
    const int tid = threadIdx.x;

    const __half* L = g_lh + (size_t)bs0 * VC_;
    // stage interleaved: per pair (j0, j0+1), transpose 8 rows via byte_perm
    for (int i = tid; i < VC_ / 2; i += 512) {
        int j0 = i * 2;
        unsigned u[8];
#pragma unroll
        for (int r = 0; r < 8; r++)
            u[r] = *(const unsigned*)(L + (size_t)r * VC_ + j0);
        uint4 e0 = make_uint4(__byte_perm(u[0], u[1], 0x5410),
                              __byte_perm(u[2], u[3], 0x5410),
                              __byte_perm(u[4], u[5], 0x5410),
                              __byte_perm(u[6], u[7], 0x5410));
        uint4 e1 = make_uint4(__byte_perm(u[0], u[1], 0x7632),
                              __byte_perm(u[2], u[3], 0x7632),
                              __byte_perm(u[4], u[5], 0x7632),
                              __byte_perm(u[6], u[7], 0x7632));
        *(uint4*)(sh + j0 * 8) = e0;
        *(uint4*)(sh + (j0 + 1) * 8) = e1;
    }
    __syncthreads();

#pragma unroll
    for (int c = 0; c < 16; c++) {
        int v0 = c * 2048 + tid * 4;
        if (v0 >= V_) break;
        const uint4* cp_ = (const uint4*)(g_codes + (size_t)v0 * K_);
        uint4 p0 = cp_[0];
        uint4 p1 = cp_[1];
        unsigned cw[8] = {p0.x, p0.y, p0.z, p0.w, p1.x, p1.y, p1.z, p1.w};

        float acc[8][4];
#pragma unroll
        for (int r = 0; r < 8; r++)
#pragma unroll
            for (int vi = 0; vi < 4; vi++) acc[r][vi] = 0.0f;

#pragma unroll
        for (int vi = 0; vi < 4; vi++) {
#pragma unroll
            for (int h = 0; h < 2; h++) {
                unsigned w = cw[vi * 2 + h];
                int ja = (w & 0xFFFF) * 8, jb = (w >> 16) * 8;
                uint4 qa = *(const uint4*)(sh + ja);
                float2 f;
                f = __half22float2(*(const __half2*)&qa.x);
                acc[0][vi] += f.x; acc[1][vi] += f.y;
                f = __half22float2(*(const __half2*)&qa.y);
                acc[2][vi] += f.x; acc[3][vi] += f.y;
                f = __half22float2(*(const __half2*)&qa.z);
                acc[4][vi] += f.x; acc[5][vi] += f.y;
                f = __half22float2(*(const __half2*)&qa.w);
                acc[6][vi] += f.x; acc[7][vi] += f.y;
                uint4 qb = *(const uint4*)(sh + jb);
                f = __half22float2(*(const __half2*)&qb.x);
                acc[0][vi] += f.x; acc[1][vi] += f.y;
                f = __half22float2(*(const __half2*)&qb.y);
                acc[2][vi] += f.x; acc[3][vi] += f.y;
                f = __half22float2(*(const __half2*)&qb.z);
                acc[4][vi] += f.x; acc[5][vi] += f.y;
                f = __half22float2(*(const __half2*)&qb.w);
                acc[6][vi] += f.x; acc[7][vi] += f.y;
            }
        }
#pragma unroll
        for (int r = 0; r < 8; r++) {
            *(float4*)(out + (size_t)(bs0 + r) * V_ + v0) =
                make_float4(acc[r][0] * 0.25f, acc[r][1] * 0.25f,
                            acc[r][2] * 0.25f, acc[r][3] * 0.25f);
        }
    }
}

// ---------------------------------------------------------------------------
// Launch
// ---------------------------------------------------------------------------
extern "C" void kernel_launch(void* const* d_in, const int* in_sizes, int n_in,
                              void* d_out, int out_size) {
    const float* x = (const float*)d_in[0];
    const float* W = (const float*)d_in[1];
    const int*   p = (const int*)d_in[2];
    const int*   a = (const int*)d_in[3];
    const int*   b = (const int*)d_in[4];
    float* out = (float*)d_out;

    hash_kernel<<<(V_ + 255) / 256, 256>>>(p, a, b);
    convert_kernel<<<(NX4 + NW4 + 255) / 256, 256>>>(x, W);

    cudaFuncSetAttribute(gemm_f16, cudaFuncAttributeMaxDynamicSharedMemorySize,
                         GEMM_SMEM);
    dim3 ggrid(VC_ / BN, BS_ / BM);   // (64, 8)
    gemm_f16<<<ggrid, 512, GEMM_SMEM>>>();

    const int gather_smem = VC_ * 8 * (int)sizeof(__half);   // 128 KB
    cudaFuncSetAttribute(gather8,
                         cudaFuncAttributeMaxDynamicSharedMemorySize, gather_smem);
    gather8<<<BS_ / 8, 512, gather_smem>>>(out);
}

// round 7
// speedup vs baseline: 1.9212x; 1.0120x over previous
#include <cuda_runtime.h>
#include <cuda_fp16.h>
#include <cstdint>

// Problem constants (fixed by the dataset)
#define B_   2
#define S_   1024
#define D_   1024
#define VC_  8192
#define K_   4
#define V_   32000
#define BS_  (B_ * S_)   // 2048

// ---------------------------------------------------------------------------
// Device-global scratch (allocation-free rule)
// ---------------------------------------------------------------------------
__device__ __half         g_lh[BS_ * VC_];      // 32 MB f16 logits
__device__ __half         g_xh[BS_ * D_];       // 4 MB  f16 X
__device__ __half         g_wh[VC_ * D_];       // 16 MB f16 W
__device__ unsigned short g_codes[V_ * K_];     // 256 KB packed hash codes

// ---------------------------------------------------------------------------
// Kernel 1: fused convert (X,W -> f16) + hash table build
// ---------------------------------------------------------------------------
#define NX4 ((BS_ * D_) / 4)   // 524288 float4
#define NW4 ((VC_ * D_) / 4)   // 2097152 float4
#define NTOT (NX4 + NW4 + V_)
__global__ __launch_bounds__(256) void prep_kernel(const float* __restrict__ X,
                                                   const float* __restrict__ W,
                                                   const int* __restrict__ p,
                                                   const int* __restrict__ a,
                                                   const int* __restrict__ b) {
    int i = blockIdx.x * blockDim.x + threadIdx.x;
    if (i < NX4) {
        float4 v = ((const float4*)X)[i];
        __half2 h0 = __floats2half2_rn(v.x, v.y);
        __half2 h1 = __floats2half2_rn(v.z, v.w);
        ((uint2*)g_xh)[i] = make_uint2(*(uint32_t*)&h0, *(uint32_t*)&h1);
    } else if (i < NX4 + NW4) {
        int j = i - NX4;
        float4 v = ((const float4*)W)[j];
        __half2 h0 = __floats2half2_rn(v.x, v.y);
        __half2 h1 = __floats2half2_rn(v.z, v.w);
        ((uint2*)g_wh)[j] = make_uint2(*(uint32_t*)&h0, *(uint32_t*)&h1);
    } else if (i < NTOT) {
        int v = i - NX4 - NW4;
#pragma unroll
        for (int k = 0; k < K_; k++) {
            unsigned int h = (unsigned int)(v * a[k] + b[k]) % (unsigned int)p[k];
            g_codes[v * K_ + k] = (unsigned short)(h & (VC_ - 1));
        }
    }
}

// ---------------------------------------------------------------------------
// Kernel 2: fp16 GEMM, 4-stage cp.async pipeline.
// Tile 256x128x32, 512 threads (8 m-warps x 2 n-warps, warp tile 32x64),
// mma.sync.m16n8k16 (fp32 accum), ldmatrix.x4 fragments (80B pitch,
// conflict-free).
// ---------------------------------------------------------------------------
#define BM 256
#define BN 128
#define BK 32
#define HPAD 40   // halves per smem row -> 80B pitch
#define NS 4      // pipeline stages

#define AS_BYTES (BM * HPAD * 2)   // 20480
#define BSB_BYTES (BN * HPAD * 2)  // 10240
#define GEMM_SMEM (NS * (AS_BYTES + BSB_BYTES))   // 122880

__device__ __forceinline__ uint32_t smem_u32(const void* p) {
    uint32_t a;
    asm("{ .reg .u64 t; cvta.to.shared.u64 t, %1; cvt.u32.u64 %0, t; }"
        : "=r"(a) : "l"(p));
    return a;
}
__device__ __forceinline__ void cpa16(uint32_t dst, const void* src) {
    asm volatile("cp.async.cg.shared.global [%0], [%1], 16;"
                 :: "r"(dst), "l"(src) : "memory");
}
#define CP_COMMIT() asm volatile("cp.async.commit_group;" ::: "memory")
#define CP_WAIT(n)  asm volatile("cp.async.wait_group %0;" :: "n"(n) : "memory")

__device__ __forceinline__ void ldmx4(uint32_t& r0, uint32_t& r1,
                                      uint32_t& r2, uint32_t& r3, uint32_t addr) {
    asm volatile("ldmatrix.sync.aligned.m8n8.x4.shared.b16 {%0,%1,%2,%3}, [%4];"
                 : "=r"(r0), "=r"(r1), "=r"(r2), "=r"(r3) : "r"(addr));
}

__global__ __launch_bounds__(512, 1) void gemm_f16(void) {
    extern __shared__ __align__(16) char sm[];
    const int tid  = threadIdx.x;
    const int lane = tid & 31;
    const int warp = tid >> 5;
    const int wm   = (warp & 7) * 32;   // 8 m-warps
    const int wn   = (warp >> 3) * 64;  // 2 n-warps
    const int g    = lane >> 2;
    const int t    = lane & 3;

    const int rowBase = blockIdx.y * BM;
    const int colBase = blockIdx.x * BN;

    const uint32_t smb = smem_u32(sm);

    const int ra = tid >> 2;            // 0..127
    const int c8 = (tid & 3) * 8;

    const __half* gA0 = g_xh + (size_t)(rowBase + ra) * D_ + c8;
    const __half* gA1 = g_xh + (size_t)(rowBase + ra + 128) * D_ + c8;
    const __half* gB  = g_wh + (size_t)(colBase + ra) * D_ + c8;
    const uint32_t stA0 = (ra * HPAD + c8) * 2;
    const uint32_t stA1 = ((ra + 128) * HPAD + c8) * 2;
    const uint32_t stB  = (ra * HPAD + c8) * 2;

#define ISSUE_STAGE(stg)                                                     \
    {                                                                        \
        int _slot = (stg) & (NS - 1);                                        \
        int _kt = (stg) * BK;                                                \
        uint32_t _sA = smb + _slot * AS_BYTES;                               \
        uint32_t _sB = smb + NS * AS_BYTES + _slot * BSB_BYTES;              \
        cpa16(_sA + stA0, gA0 + _kt);                                        \
        cpa16(_sA + stA1, gA1 + _kt);                                        \
        cpa16(_sB + stB,  gB  + _kt);                                        \
        CP_COMMIT();                                                         \
    }

    const int aRow = wm + (lane & 7) + ((lane & 8) ? 8 : 0);
    const int aCol = (lane & 16) ? 8 : 0;
    const int bRow = wn + (lane & 7) + ((lane & 16) ? 8 : 0);
    const int bCol = ((lane & 8) ? 8 : 0);

    float acc[2][8][4];
#pragma unroll
    for (int mt = 0; mt < 2; mt++)
#pragma unroll
        for (int nt = 0; nt < 8; nt++)
#pragma unroll
            for (int i = 0; i < 4; i++) acc[mt][nt][i] = 0.0f;

    ISSUE_STAGE(0);
    ISSUE_STAGE(1);
    ISSUE_STAGE(2);

    const int NCHUNK = D_ / BK;   // 32
    for (int c = 0; c < NCHUNK; c++) {
        if (c < NCHUNK - 2) { CP_WAIT(2); } else { CP_WAIT(0); }
        __syncthreads();

        const int slot = c & (NS - 1);
        uint32_t asBase = smb + slot * AS_BYTES;
        uint32_t bsBase = smb + NS * AS_BYTES + slot * BSB_BYTES;

#pragma unroll
        for (int s = 0; s < 2; s++) {
            uint32_t af[2][4];
            uint32_t bf[8][2];
#pragma unroll
            for (int mt = 0; mt < 2; mt++) {
                uint32_t addr = asBase +
                    (((aRow + mt * 16) * HPAD) + (aCol + s * 16)) * 2;
                ldmx4(af[mt][0], af[mt][1], af[mt][2], af[mt][3], addr);
            }
#pragma unroll
            for (int ntp = 0; ntp < 4; ntp++) {
                uint32_t addr = bsBase +
                    (((bRow + ntp * 16) * HPAD) + (bCol + s * 16)) * 2;
                ldmx4(bf[2 * ntp][0], bf[2 * ntp][1],
                      bf[2 * ntp + 1][0], bf[2 * ntp + 1][1], addr);
            }
#pragma unroll
            for (int mt = 0; mt < 2; mt++)
#pragma unroll
                for (int nt = 0; nt < 8; nt++) {
                    asm volatile(
                        "mma.sync.aligned.m16n8k16.row.col.f32.f16.f16.f32 "
                        "{%0,%1,%2,%3},{%4,%5,%6,%7},{%8,%9},{%0,%1,%2,%3};"
                        : "+f"(acc[mt][nt][0]), "+f"(acc[mt][nt][1]),
                          "+f"(acc[mt][nt][2]), "+f"(acc[mt][nt][3])
                        : "r"(af[mt][0]), "r"(af[mt][1]),
                          "r"(af[mt][2]), "r"(af[mt][3]),
                          "r"(bf[nt][0]), "r"(bf[nt][1]));
                }
        }

        if (c + NS - 1 < NCHUNK) ISSUE_STAGE(c + NS - 1);
    }

    // epilogue: f16 logits
#pragma unroll
    for (int mt = 0; mt < 2; mt++) {
#pragma unroll
        for (int nt = 0; nt < 8; nt++) {
            int r = rowBase + wm + mt * 16 + g;
            int c = colBase + wn + nt * 8 + 2 * t;
            __half2 h0 = __floats2half2_rn(acc[mt][nt][0], acc[mt][nt][1]);
            __half2 h1 = __floats2half2_rn(acc[mt][nt][2], acc[mt][nt][3]);
            *(uint32_t*)(g_lh + (size_t)r * VC_ + c)       = *(uint32_t*)&h0;
            *(uint32_t*)(g_lh + (size_t)(r + 8) * VC_ + c) = *(uint32_t*)&h1;
        }
    }
#undef ISSUE_STAGE
}

// ---------------------------------------------------------------------------
// Kernel 3: gather.  FOUR (b,s) rows per CTA, f16, interleaved [j][r0..r3]
// in 64 KB smem; 1024 threads, 2 CTAs/SM -> 64 warps/SM.
// One LDS.64 serves 4 rows x 1 hash code.
// ---------------------------------------------------------------------------
__global__ __launch_bounds__(1024, 2) void gather4(float* __restrict__ out) {
    extern __shared__ __half sh[];       // 8192 * 4 halves = 64 KB
    const int bs0 = blockIdx.x * 4;
    const int tid = threadIdx.x;

    const __half* L = g_lh + (size_t)bs0 * VC_;
    // stage interleaved: thread handles j0 = 2*i, transposes 4 rows
    for (int i = tid; i < VC_ / 2; i += 1024) {
        int j0 = i * 2;
        unsigned u0 = *(const unsigned*)(L + j0);
        unsigned u1 = *(const unsigned*)(L + VC_ + j0);
        unsigned u2 = *(const unsigned*)(L + 2 * VC_ + j0);
        unsigned u3 = *(const unsigned*)(L + 3 * VC_ + j0);
        *(uint2*)(sh + j0 * 4) =
            make_uint2(__byte_perm(u0, u1, 0x5410), __byte_perm(u2, u3, 0x5410));
        *(uint2*)(sh + (j0 + 1) * 4) =
            make_uint2(__byte_perm(u0, u1, 0x7632), __byte_perm(u2, u3, 0x7632));
    }
    __syncthreads();

    float* o0 = out + (size_t)bs0 * V_;
    float* o1 = o0 + V_;
    float* o2 = o1 + V_;
    float* o3 = o2 + V_;

#pragma unroll
    for (int c = 0; c < 8; c++) {
        int v0 = c * 4096 + tid * 4;
        if (v0 >= V_) break;
        const uint4* cp = (const uint4*)(g_codes + (size_t)v0 * K_);
        uint4 p0 = cp[0];
        uint4 p1 = cp[1];
        unsigned cw[8] = {p0.x, p0.y, p0.z, p0.w, p1.x, p1.y, p1.z, p1.w};

        float s0[4], s1[4], s2[4], s3[4];
#pragma unroll
        for (int vi = 0; vi < 4; vi++) {
            float a0 = 0.f, a1 = 0.f, a2 = 0.f, a3 = 0.f;
#pragma unroll
            for (int h = 0; h < 2; h++) {
                unsigned w = cw[vi * 2 + h];
                int ja = w & 0xFFFF, jb = w >> 16;
                uint2 qa = *(const uint2*)(sh + ja * 4);
                float2 fa01 = __half22float2(*(const __half2*)&qa.x);
                float2 fa23 = __half22float2(*(const __half2*)&qa.y);
                a0 += fa01.x; a1 += fa01.y; a2 += fa23.x; a3 += fa23.y;
                uint2 qb = *(const uint2*)(sh + jb * 4);
                float2 fb01 = __half22float2(*(const __half2*)&qb.x);
                float2 fb23 = __half22float2(*(const __half2*)&qb.y);
                a0 += fb01.x; a1 += fb01.y; a2 += fb23.x; a3 += fb23.y;
            }
            s0[vi] = a0 * 0.25f; s1[vi] = a1 * 0.25f;
            s2[vi] = a2 * 0.25f; s3[vi] = a3 * 0.25f;
        }
        *(float4*)(o0 + v0) = make_float4(s0[0], s0[1], s0[2], s0[3]);
        *(float4*)(o1 + v0) = make_float4(s1[0], s1[1], s1[2], s1[3]);
        *(float4*)(o2 + v0) = make_float4(s2[0], s2[1], s2[2], s2[3]);
        *(float4*)(o3 + v0) = make_float4(s3[0], s3[1], s3[2], s3[3]);
    }
}

// ---------------------------------------------------------------------------
// Launch
// ---------------------------------------------------------------------------
extern "C" void kernel_launch(void* const* d_in, const int* in_sizes, int n_in,
                              void* d_out, int out_size) {
    const float* x = (const float*)d_in[0];
    const float* W = (const float*)d_in[1];
    const int*   p = (const int*)d_in[2];
    const int*   a = (const int*)d_in[3];
    const int*   b = (const int*)d_in[4];
    float* out = (float*)d_out;

    prep_kernel<<<(NTOT + 255) / 256, 256>>>(x, W, p, a, b);

    cudaFuncSetAttribute(gemm_f16, cudaFuncAttributeMaxDynamicSharedMemorySize,
                         GEMM_SMEM);
    dim3 ggrid(VC_ / BN, BS_ / BM);   // (64, 8)
    gemm_f16<<<ggrid, 512, GEMM_SMEM>>>();

    const int gather_smem = VC_ * 4 * (int)sizeof(__half);   // 64 KB
    cudaFuncSetAttribute(gather4,
                         cudaFuncAttributeMaxDynamicSharedMemorySize, gather_smem);
    gather4<<<BS_ / 4, 1024, gather_smem>>>(out);
}

// round 8
// speedup vs baseline: 2.1278x; 1.1075x over previous
#include <cuda_runtime.h>
#include <cuda_fp16.h>
#include <cstdint>

// Problem constants (fixed by the dataset)
#define B_   2
#define S_   1024
#define D_   1024
#define VC_  8192
#define K_   4
#define V_   32000
#define BS_  (B_ * S_)   // 2048

// ---------------------------------------------------------------------------
// Device-global scratch (allocation-free rule)
// ---------------------------------------------------------------------------
__device__ __half         g_lh[BS_ * VC_];      // 32 MB f16 logits
__device__ __half         g_xh[BS_ * D_];       // 4 MB  f16 X
__device__ __half         g_wh[VC_ * D_];       // 16 MB f16 W
__device__ unsigned short g_codes[V_ * K_];     // 256 KB packed hash codes

// ---------------------------------------------------------------------------
// Kernel 1: fused convert (X,W -> f16) + hash table build
// ---------------------------------------------------------------------------
#define NX4 ((BS_ * D_) / 4)   // 524288 float4
#define NW4 ((VC_ * D_) / 4)   // 2097152 float4
#define NTOT (NX4 + NW4 + V_)
__global__ __launch_bounds__(256) void prep_kernel(const float* __restrict__ X,
                                                   const float* __restrict__ W,
                                                   const int* __restrict__ p,
                                                   const int* __restrict__ a,
                                                   const int* __restrict__ b) {
    int i = blockIdx.x * blockDim.x + threadIdx.x;
    if (i < NX4) {
        float4 v = ((const float4*)X)[i];
        __half2 h0 = __floats2half2_rn(v.x, v.y);
        __half2 h1 = __floats2half2_rn(v.z, v.w);
        ((uint2*)g_xh)[i] = make_uint2(*(uint32_t*)&h0, *(uint32_t*)&h1);
    } else if (i < NX4 + NW4) {
        int j = i - NX4;
        float4 v = ((const float4*)W)[j];
        __half2 h0 = __floats2half2_rn(v.x, v.y);
        __half2 h1 = __floats2half2_rn(v.z, v.w);
        ((uint2*)g_wh)[j] = make_uint2(*(uint32_t*)&h0, *(uint32_t*)&h1);
    } else if (i < NTOT) {
        int v = i - NX4 - NW4;
#pragma unroll
        for (int k = 0; k < K_; k++) {
            unsigned int h = (unsigned int)(v * a[k] + b[k]) % (unsigned int)p[k];
            g_codes[v * K_ + k] = (unsigned short)(h & (VC_ - 1));
        }
    }
}

// ---------------------------------------------------------------------------
// Kernel 2: fp16 GEMM, 4-stage cp.async pipeline, 2 CTAs/SM.
// Tile 128x128x32, 256 threads (4 m-warps x 2 n-warps, warp tile 32x64),
// mma.sync.m16n8k16 (fp32 accum), ldmatrix.x4 fragments (80B pitch).
// ---------------------------------------------------------------------------
#define BM 128
#define BN 128
#define BK 32
#define HPAD 40   // halves per smem row -> 80B pitch
#define NS 4      // pipeline stages

#define AS_BYTES (BM * HPAD * 2)   // 10240
#define BSB_BYTES (BN * HPAD * 2)  // 10240
#define GEMM_SMEM (NS * (AS_BYTES + BSB_BYTES))   // 81920

__device__ __forceinline__ uint32_t smem_u32(const void* p) {
    uint32_t a;
    asm("{ .reg .u64 t; cvta.to.shared.u64 t, %1; cvt.u32.u64 %0, t; }"
        : "=r"(a) : "l"(p));
    return a;
}
__device__ __forceinline__ void cpa16(uint32_t dst, const void* src) {
    asm volatile("cp.async.cg.shared.global [%0], [%1], 16;"
                 :: "r"(dst), "l"(src) : "memory");
}
#define CP_COMMIT() asm volatile("cp.async.commit_group;" ::: "memory")
#define CP_WAIT(n)  asm volatile("cp.async.wait_group %0;" :: "n"(n) : "memory")

__device__ __forceinline__ void ldmx4(uint32_t& r0, uint32_t& r1,
                                      uint32_t& r2, uint32_t& r3, uint32_t addr) {
    asm volatile("ldmatrix.sync.aligned.m8n8.x4.shared.b16 {%0,%1,%2,%3}, [%4];"
                 : "=r"(r0), "=r"(r1), "=r"(r2), "=r"(r3) : "r"(addr));
}

__global__ __launch_bounds__(256, 2) void gemm_f16(void) {
    extern __shared__ __align__(16) char sm[];
    const int tid  = threadIdx.x;
    const int lane = tid & 31;
    const int warp = tid >> 5;
    const int wm   = (warp & 3) * 32;   // 4 m-warps
    const int wn   = (warp >> 2) * 64;  // 2 n-warps
    const int g    = lane >> 2;
    const int t    = lane & 3;

    const int rowBase = blockIdx.y * BM;
    const int colBase = blockIdx.x * BN;

    const uint32_t smb = smem_u32(sm);

    // copy coords: A/B each 128 rows x 32 halves = 512 uint4; 2 per thread
    const int ra = tid >> 2;            // 0..63 (+64 for second)
    const int c8 = (tid & 3) * 8;

    const __half* gA0 = g_xh + (size_t)(rowBase + ra) * D_ + c8;
    const __half* gA1 = g_xh + (size_t)(rowBase + ra + 64) * D_ + c8;
    const __half* gB0 = g_wh + (size_t)(colBase + ra) * D_ + c8;
    const __half* gB1 = g_wh + (size_t)(colBase + ra + 64) * D_ + c8;
    const uint32_t st0 = (ra * HPAD + c8) * 2;
    const uint32_t st1 = ((ra + 64) * HPAD + c8) * 2;

#define ISSUE_STAGE(stg)                                                     \
    {                                                                        \
        int _slot = (stg) & (NS - 1);                                        \
        int _kt = (stg) * BK;                                                \
        uint32_t _sA = smb + _slot * AS_BYTES;                               \
        uint32_t _sB = smb + NS * AS_BYTES + _slot * BSB_BYTES;              \
        cpa16(_sA + st0, gA0 + _kt);                                         \
        cpa16(_sA + st1, gA1 + _kt);                                         \
        cpa16(_sB + st0, gB0 + _kt);                                         \
        cpa16(_sB + st1, gB1 + _kt);                                         \
        CP_COMMIT();                                                         \
    }

    const int aRow = wm + (lane & 7) + ((lane & 8) ? 8 : 0);
    const int aCol = (lane & 16) ? 8 : 0;
    const int bRow = wn + (lane & 7) + ((lane & 16) ? 8 : 0);
    const int bCol = ((lane & 8) ? 8 : 0);

    float acc[2][8][4];
#pragma unroll
    for (int mt = 0; mt < 2; mt++)
#pragma unroll
        for (int nt = 0; nt < 8; nt++)
#pragma unroll
            for (int i = 0; i < 4; i++) acc[mt][nt][i] = 0.0f;

    ISSUE_STAGE(0);
    ISSUE_STAGE(1);
    ISSUE_STAGE(2);

    const int NCHUNK = D_ / BK;   // 32
    for (int c = 0; c < NCHUNK; c++) {
        if (c < NCHUNK - 2) { CP_WAIT(2); } else { CP_WAIT(0); }
        __syncthreads();

        const int slot = c & (NS - 1);
        uint32_t asBase = smb + slot * AS_BYTES;
        uint32_t bsBase = smb + NS * AS_BYTES + slot * BSB_BYTES;

#pragma unroll
        for (int s = 0; s < 2; s++) {
            uint32_t af[2][4];
            uint32_t bf[8][2];
#pragma unroll
            for (int mt = 0; mt < 2; mt++) {
                uint32_t addr = asBase +
                    (((aRow + mt * 16) * HPAD) + (aCol + s * 16)) * 2;
                ldmx4(af[mt][0], af[mt][1], af[mt][2], af[mt][3], addr);
            }
#pragma unroll
            for (int ntp = 0; ntp < 4; ntp++) {
                uint32_t addr = bsBase +
                    (((bRow + ntp * 16) * HPAD) + (bCol + s * 16)) * 2;
                ldmx4(bf[2 * ntp][0], bf[2 * ntp][1],
                      bf[2 * ntp + 1][0], bf[2 * ntp + 1][1], addr);
            }
#pragma unroll
            for (int mt = 0; mt < 2; mt++)
#pragma unroll
                for (int nt = 0; nt < 8; nt++) {
                    asm volatile(
                        "mma.sync.aligned.m16n8k16.row.col.f32.f16.f16.f32 "
                        "{%0,%1,%2,%3},{%4,%5,%6,%7},{%8,%9},{%0,%1,%2,%3};"
                        : "+f"(acc[mt][nt][0]), "+f"(acc[mt][nt][1]),
                          "+f"(acc[mt][nt][2]), "+f"(acc[mt][nt][3])
                        : "r"(af[mt][0]), "r"(af[mt][1]),
                          "r"(af[mt][2]), "r"(af[mt][3]),
                          "r"(bf[nt][0]), "r"(bf[nt][1]));
                }
        }

        if (c + NS - 1 < NCHUNK) ISSUE_STAGE(c + NS - 1);
    }

    // epilogue: f16 logits
#pragma unroll
    for (int mt = 0; mt < 2; mt++) {
#pragma unroll
        for (int nt = 0; nt < 8; nt++) {
            int r = rowBase + wm + mt * 16 + g;
            int c = colBase + wn + nt * 8 + 2 * t;
            __half2 h0 = __floats2half2_rn(acc[mt][nt][0], acc[mt][nt][1]);
            __half2 h1 = __floats2half2_rn(acc[mt][nt][2], acc[mt][nt][3]);
            *(uint32_t*)(g_lh + (size_t)r * VC_ + c)       = *(uint32_t*)&h0;
            *(uint32_t*)(g_lh + (size_t)(r + 8) * VC_ + c) = *(uint32_t*)&h1;
        }
    }
#undef ISSUE_STAGE
}

// ---------------------------------------------------------------------------
// Kernel 3: gather.  FOUR (b,s) rows per CTA, f16, interleaved [j][r0..r3]
// in 64 KB smem; 1024 threads.  __ldcs staging (read-once), __stwt output
// (streaming: keep logits + code table resident in L2).
// ---------------------------------------------------------------------------
__global__ __launch_bounds__(1024, 2) void gather4(float* __restrict__ out) {
    extern __shared__ __half sh[];       // 8192 * 4 halves = 64 KB
    const int bs0 = blockIdx.x * 4;
    const int tid = threadIdx.x;

    const __half* L = g_lh + (size_t)bs0 * VC_;
    for (int i = tid; i < VC_ / 2; i += 1024) {
        int j0 = i * 2;
        unsigned u0 = __ldcs((const unsigned*)(L + j0));
        unsigned u1 = __ldcs((const unsigned*)(L + VC_ + j0));
        unsigned u2 = __ldcs((const unsigned*)(L + 2 * VC_ + j0));
        unsigned u3 = __ldcs((const unsigned*)(L + 3 * VC_ + j0));
        *(uint2*)(sh + j0 * 4) =
            make_uint2(__byte_perm(u0, u1, 0x5410), __byte_perm(u2, u3, 0x5410));
        *(uint2*)(sh + (j0 + 1) * 4) =
            make_uint2(__byte_perm(u0, u1, 0x7632), __byte_perm(u2, u3, 0x7632));
    }
    __syncthreads();

    float* o0 = out + (size_t)bs0 * V_;
    float* o1 = o0 + V_;
    float* o2 = o1 + V_;
    float* o3 = o2 + V_;

#pragma unroll
    for (int c = 0; c < 8; c++) {
        int v0 = c * 4096 + tid * 4;
        if (v0 >= V_) break;
        const uint4* cp = (const uint4*)(g_codes + (size_t)v0 * K_);
        uint4 p0 = cp[0];
        uint4 p1 = cp[1];
        unsigned cw[8] = {p0.x, p0.y, p0.z, p0.w, p1.x, p1.y, p1.z, p1.w};

        float s0[4], s1[4], s2[4], s3[4];
#pragma unroll
        for (int vi = 0; vi < 4; vi++) {
            float a0 = 0.f, a1 = 0.f, a2 = 0.f, a3 = 0.f;
#pragma unroll
            for (int h = 0; h < 2; h++) {
                unsigned w = cw[vi * 2 + h];
                int ja = w & 0xFFFF, jb = w >> 16;
                uint2 qa = *(const uint2*)(sh + ja * 4);
                float2 fa01 = __half22float2(*(const __half2*)&qa.x);
                float2 fa23 = __half22float2(*(const __half2*)&qa.y);
                a0 += fa01.x; a1 += fa01.y; a2 += fa23.x; a3 += fa23.y;
                uint2 qb = *(const uint2*)(sh + jb * 4);
                float2 fb01 = __half22float2(*(const __half2*)&qb.x);
                float2 fb23 = __half22float2(*(const __half2*)&qb.y);
                a0 += fb01.x; a1 += fb01.y; a2 += fb23.x; a3 += fb23.y;
            }
            s0[vi] = a0 * 0.25f; s1[vi] = a1 * 0.25f;
            s2[vi] = a2 * 0.25f; s3[vi] = a3 * 0.25f;
        }
        __stwt((float4*)(o0 + v0), make_float4(s0[0], s0[1], s0[2], s0[3]));
        __stwt((float4*)(o1 + v0), make_float4(s1[0], s1[1], s1[2], s1[3]));
        __stwt((float4*)(o2 + v0), make_float4(s2[0], s2[1], s2[2], s2[3]));
        __stwt((float4*)(o3 + v0), make_float4(s3[0], s3[1], s3[2], s3[3]));
    }
}

// ---------------------------------------------------------------------------
// Launch
// ---------------------------------------------------------------------------
extern "C" void kernel_launch(void* const* d_in, const int* in_sizes, int n_in,
                              void* d_out, int out_size) {
    const float* x = (const float*)d_in[0];
    const float* W = (const float*)d_in[1];
    const int*   p = (const int*)d_in[2];
    const int*   a = (const int*)d_in[3];
    const int*   b = (const int*)d_in[4];
    float* out = (float*)d_out;

    prep_kernel<<<(NTOT + 255) / 256, 256>>>(x, W, p, a, b);

    cudaFuncSetAttribute(gemm_f16, cudaFuncAttributeMaxDynamicSharedMemorySize,
                         GEMM_SMEM);
    dim3 ggrid(VC_ / BN, BS_ / BM);   // (64, 16)
    gemm_f16<<<ggrid, 256, GEMM_SMEM>>>();

    const int gather_smem = VC_ * 4 * (int)sizeof(__half);   // 64 KB
    cudaFuncSetAttribute(gather4,
                         cudaFuncAttributeMaxDynamicSharedMemorySize, gather_smem);
    gather4<<<BS_ / 4, 1024, gather_smem>>>(out);
}